// round 5
// baseline (speedup 1.0000x reference)
#include <cuda_runtime.h>
#include <cuda_bf16.h>
#include <math_constants.h>

// ---------------------------------------------------------------------------
// HybridConv: out[n] = MLP(RBF(sigmoid(dot(data[n], conv_w) + conv_b)))
// Everything after the conv is a scalar function of act = sigmoid(logit).
// Tabulated on 4096 intervals, packed 1 word/entry:
//   bits[11..31]: 21-bit quantized f (left endpoint), bits[0..10]: 11-bit df.
// TWO launches: fused build+pack (last-block epilogue), then streaming main:
// 4x LDG.128 -> dot -> sigmoid -> one LDS.32 + decode -> STG.128.
// NOTE: all warp shuffles are executed by EVERY lane of the warp (entry is
// clamped, never guarded at sub-warp granularity) — sm_103a shfl.sync with
// missing lanes deadlocks.
// ---------------------------------------------------------------------------

#define NTAB   4096
#define BASIS  8
#define HIDDEN 16

__device__ float        g_ftab[NTAB + 1];
__device__ unsigned int g_ptab[NTAB];
__device__ float        g_params[4];   // fmin, fscale, dscale
__device__ int          g_count;       // zero-init; last block resets to 0

// ---- fused build (half-warp per entry) + pack (last block) ----------------
__global__ void __launch_bounds__(256)
build_pack_kernel(const float* __restrict__ basis,
                  const float* __restrict__ w1,
                  const float* __restrict__ b1,
                  const float* __restrict__ w2,
                  const float* __restrict__ b2) {
    int gtid   = blockIdx.x * blockDim.x + threadIdx.x;
    int entry0 = gtid >> 4;                      // half-warp id (true)
    int entry  = entry0 <= NTAB ? entry0 : NTAB; // clamped: all lanes compute
    int h      = gtid & 15;                      // hidden unit

    {
        float a = (float)entry * (1.0f / (float)NTAB);
        float p = b1[h];
#pragma unroll
        for (int j = 0; j < BASIS; j++) {
            float s = 0.0f;
#pragma unroll
            for (int k = 0; k < 4; k++) {
                float d = a - basis[j * 4 + k];
                s = fmaf(d, d, s);
            }
            p = fmaf(expf(-s), w1[j * HIDDEN + h], p);   // GAMMA = 1, precise
        }
        float v = tanhf(p) * w2[h];                      // precise tanh
        // 16-lane reduce within each half-warp; ALL 32 lanes participate.
#pragma unroll
        for (int off = 8; off; off >>= 1)
            v += __shfl_xor_sync(0xFFFFFFFFu, v, off);
        if (h == 0 && entry0 <= NTAB) g_ftab[entry0] = v + b2[0];
    }

    // ---- last-block epilogue: range discovery + pack ----
    __shared__ int s_last;
    __threadfence();
    __syncthreads();
    if (threadIdx.x == 0)
        s_last = (atomicAdd(&g_count, 1) == (int)gridDim.x - 1);
    __syncthreads();
    if (!s_last) return;

    __shared__ float s_min[256], s_max[256], s_dmx[256];
    int tid = threadIdx.x;
    float fmin = CUDART_INF_F, fmax = -CUDART_INF_F, dmax = 0.0f;
    for (int j = tid; j <= NTAB; j += 256) {
        float v = g_ftab[j];
        fmin = fminf(fmin, v);
        fmax = fmaxf(fmax, v);
    }
    for (int j = tid; j < NTAB; j += 256)
        dmax = fmaxf(dmax, fabsf(g_ftab[j + 1] - g_ftab[j]));
    s_min[tid] = fmin; s_max[tid] = fmax; s_dmx[tid] = dmax;
    __syncthreads();
    for (int off = 128; off; off >>= 1) {
        if (tid < off) {
            s_min[tid] = fminf(s_min[tid], s_min[tid + off]);
            s_max[tid] = fmaxf(s_max[tid], s_max[tid + off]);
            s_dmx[tid] = fmaxf(s_dmx[tid], s_dmx[tid + off]);
        }
        __syncthreads();
    }
    fmin = s_min[0];
    float range  = fmaxf(s_max[0] - fmin, 1e-30f);
    float fscale = range * (1.0f / 2097151.0f);                  // 21-bit
    float dscale = fmaxf(s_dmx[0], 1e-30f) * (1.0f / 1023.0f);   // 11-bit signed

    if (tid == 0) {
        g_params[0] = fmin;
        g_params[1] = fscale;
        g_params[2] = dscale;
        g_count = 0;                 // reset: deterministic across replays
    }

    float inv_f = 1.0f / fscale;
    float inv_d = 1.0f / dscale;
    for (int j = tid; j < NTAB; j += 256) {
        float f0 = g_ftab[j];
        float df = g_ftab[j + 1] - f0;
        int qf = __float2int_rn((f0 - fmin) * inv_f);
        qf = max(0, min(qf, 2097151));
        int qd = __float2int_rn(df * inv_d);
        qd = max(-1024, min(qd, 1023));
        g_ptab[j] = ((unsigned)qf << 11) | ((unsigned)qd & 0x7FFu);
    }
}

// ---- main streaming pass --------------------------------------------------
__device__ __forceinline__ float table_eval(float logit, float fmin,
                                            float fscale, float dscale,
                                            const unsigned* __restrict__ stab) {
    float a = __fdividef(1.0f, 1.0f + __expf(-logit));   // 2 MUFU
    float t = a * (float)NTAB;
    int   j = __float2int_rd(t);
    j = (j > NTAB - 1) ? (NTAB - 1) : j;
    j = (j < 0) ? 0 : j;
    float frac = t - (float)j;
    unsigned w = stab[j];                                // one LDS.32
    float f = fmaf((float)(w >> 11), fscale, fmin);
    float d = (float)((int)(w << 21) >> 21) * dscale;
    return fmaf(frac, d, f);
}

__global__ void __launch_bounds__(256)
hybridconv_main_kernel(const float4* __restrict__ data,
                       const float* __restrict__ conv_w,
                       const float* __restrict__ conv_b,
                       float4* __restrict__ out, int n4, int n) {
    __shared__ unsigned stab[NTAB];
    {   // stage 16KB table with uint4 loads
        const uint4* src = (const uint4*)g_ptab;
        uint4* dst = (uint4*)stab;
        for (int j = threadIdx.x; j < NTAB / 4; j += blockDim.x)
            dst[j] = src[j];
    }
    const float w0 = conv_w[0], w1 = conv_w[1];
    const float w2 = conv_w[2], w3 = conv_w[3];
    const float bb = conv_b[0];
    const float fmin   = g_params[0];
    const float fscale = g_params[1];
    const float dscale = g_params[2];
    __syncthreads();

    const int stride = gridDim.x * blockDim.x;
    int gid = blockIdx.x * blockDim.x + threadIdx.x;

#pragma unroll 2
    for (int i = gid; i < n4; i += stride) {
        const float4* p = data + 4 * i;
        float4 v0 = p[0];
        float l0 = fmaf(v0.x, w0, fmaf(v0.y, w1, fmaf(v0.z, w2, fmaf(v0.w, w3, bb))));
        float4 v1 = p[1];
        float l1 = fmaf(v1.x, w0, fmaf(v1.y, w1, fmaf(v1.z, w2, fmaf(v1.w, w3, bb))));
        float4 v2 = p[2];
        float l2 = fmaf(v2.x, w0, fmaf(v2.y, w1, fmaf(v2.z, w2, fmaf(v2.w, w3, bb))));
        float4 v3 = p[3];
        float l3 = fmaf(v3.x, w0, fmaf(v3.y, w1, fmaf(v3.z, w2, fmaf(v3.w, w3, bb))));
        float4 r;
        r.x = table_eval(l0, fmin, fscale, dscale, stab);
        r.y = table_eval(l1, fmin, fscale, dscale, stab);
        r.z = table_eval(l2, fmin, fscale, dscale, stab);
        r.w = table_eval(l3, fmin, fscale, dscale, stab);
        out[i] = r;
    }

    // defensive tail (empty when n % 4 == 0)
    const float* sdata = (const float*)data;
    float* sout = (float*)out;
    for (int k = 4 * n4 + gid; k < n; k += stride) {
        float4 v = ((const float4*)sdata)[k];
        float l = fmaf(v.x, w0, fmaf(v.y, w1, fmaf(v.z, w2, fmaf(v.w, w3, bb))));
        sout[k] = table_eval(l, fmin, fscale, dscale, stab);
    }
}

extern "C" void kernel_launch(void* const* d_in, const int* in_sizes, int n_in,
                              void* d_out, int out_size) {
    const float* data   = (const float*)d_in[0];   // [N, 2, 2]
    const float* conv_w = (const float*)d_in[1];   // [2, 2]
    const float* conv_b = (const float*)d_in[2];   // [1]
    const float* basis  = (const float*)d_in[3];   // [8, 4]
    const float* w1     = (const float*)d_in[4];   // [8, 16]
    const float* b1     = (const float*)d_in[5];   // [16]
    const float* w2     = (const float*)d_in[6];   // [16, 1]
    const float* b2     = (const float*)d_in[7];   // [1]

    const int n  = in_sizes[0] / 4;  // patches
    const int n4 = n / 4;

    // (NTAB+1) entries * 16 threads = 65552 -> 257 blocks of 256
    int bblocks = ((NTAB + 1) * 16 + 255) / 256;
    build_pack_kernel<<<bblocks, 256>>>(basis, w1, b1, w2, b2);

    // 1216 blocks = 8 CTAs/SM on 152 SMs
    hybridconv_main_kernel<<<1216, 256>>>(
        (const float4*)data, conv_w, conv_b, (float4*)d_out, n4, n);
}

// round 6
// speedup vs baseline: 1.2452x; 1.2452x over previous
#include <cuda_runtime.h>
#include <cuda_bf16.h>

// ---------------------------------------------------------------------------
// HybridConv: out[n] = MLP(RBF(sigmoid(dot(data[n], conv_w) + conv_b)))
// Everything after the conv is a scalar function of act = sigmoid(logit).
// Tabulated on 2048 intervals (raw f32 endpoints in gmem; {f, df} staged to
// 16KB shared). TWO cheap launches:
//   1. build: half-warp per entry, fast __expf + tanh.approx  (~1.3us)
//   2. main:  4x LDG.128 -> dot -> sigmoid -> smem lerp -> STG.128
// No global sync, no pack stage, no single-block serial epilogue.
// All warp shuffles execute on every lane (entry clamped, never skipped at
// sub-warp granularity — divergent shfl.sync deadlocks on sm_103a).
// ---------------------------------------------------------------------------

#define NTAB   2048
#define BASIS  8
#define HIDDEN 16

__device__ float g_ftab[NTAB + 1];

__device__ __forceinline__ float fast_tanh(float x) {
    float y;
    asm("tanh.approx.f32 %0, %1;" : "=f"(y) : "f"(x));
    return y;
}

// ---- build: one half-warp (16 lanes = 16 hidden units) per table entry ----
__global__ void __launch_bounds__(256)
build_table_kernel(const float* __restrict__ basis,
                   const float* __restrict__ w1,
                   const float* __restrict__ b1,
                   const float* __restrict__ w2,
                   const float* __restrict__ b2) {
    int gtid   = blockIdx.x * blockDim.x + threadIdx.x;
    int entry0 = gtid >> 4;                       // true entry id
    int entry  = entry0 <= NTAB ? entry0 : NTAB;  // clamped: all lanes compute
    int h      = gtid & 15;                       // hidden unit

    float a = (float)entry * (1.0f / (float)NTAB);
    float p = b1[h];
#pragma unroll
    for (int j = 0; j < BASIS; j++) {
        float s = 0.0f;
#pragma unroll
        for (int k = 0; k < 4; k++) {
            float d = a - basis[j * 4 + k];
            s = fmaf(d, d, s);
        }
        p = fmaf(__expf(-s), w1[j * HIDDEN + h], p);   // GAMMA = 1
    }
    float v = fast_tanh(p) * w2[h];
    // 16-lane reduce within each half-warp; ALL 32 lanes participate.
#pragma unroll
    for (int off = 8; off; off >>= 1)
        v += __shfl_xor_sync(0xFFFFFFFFu, v, off);
    if (h == 0 && entry0 <= NTAB) g_ftab[entry0] = v + b2[0];
}

// ---- main streaming pass --------------------------------------------------
__device__ __forceinline__ float table_eval(float logit,
                                            const float2* __restrict__ stab) {
    float a = __fdividef(1.0f, 1.0f + __expf(-logit));   // 2 MUFU
    float t = a * (float)NTAB;
    int   j = __float2int_rd(t);
    j = (j > NTAB - 1) ? (NTAB - 1) : j;
    j = (j < 0) ? 0 : j;
    float frac = t - (float)j;
    float2 e = stab[j];                                  // one LDS.64
    return fmaf(frac, e.y, e.x);
}

__global__ void __launch_bounds__(256)
hybridconv_main_kernel(const float4* __restrict__ data,
                       const float* __restrict__ conv_w,
                       const float* __restrict__ conv_b,
                       float4* __restrict__ out, int n4, int n) {
    __shared__ float2 stab[NTAB];
    // stage table as {f, delta}
    for (int j = threadIdx.x; j < NTAB; j += blockDim.x) {
        float f0 = g_ftab[j];
        float f1 = g_ftab[j + 1];
        stab[j] = make_float2(f0, f1 - f0);
    }
    const float w0 = conv_w[0], w1 = conv_w[1];
    const float w2 = conv_w[2], w3 = conv_w[3];
    const float bb = conv_b[0];
    __syncthreads();

    const int stride = gridDim.x * blockDim.x;
    int gid = blockIdx.x * blockDim.x + threadIdx.x;

#pragma unroll 2
    for (int i = gid; i < n4; i += stride) {
        const float4* p = data + 4 * i;
        float4 v0 = __ldcs(p + 0);
        float l0 = fmaf(v0.x, w0, fmaf(v0.y, w1, fmaf(v0.z, w2, fmaf(v0.w, w3, bb))));
        float4 v1 = __ldcs(p + 1);
        float l1 = fmaf(v1.x, w0, fmaf(v1.y, w1, fmaf(v1.z, w2, fmaf(v1.w, w3, bb))));
        float4 v2 = __ldcs(p + 2);
        float l2 = fmaf(v2.x, w0, fmaf(v2.y, w1, fmaf(v2.z, w2, fmaf(v2.w, w3, bb))));
        float4 v3 = __ldcs(p + 3);
        float l3 = fmaf(v3.x, w0, fmaf(v3.y, w1, fmaf(v3.z, w2, fmaf(v3.w, w3, bb))));
        float4 r;
        r.x = table_eval(l0, stab);
        r.y = table_eval(l1, stab);
        r.z = table_eval(l2, stab);
        r.w = table_eval(l3, stab);
        __stcs(&out[i], r);
    }

    // defensive tail (empty when n % 4 == 0)
    const float* sdata = (const float*)data;
    float* sout = (float*)out;
    for (int k = 4 * n4 + gid; k < n; k += stride) {
        float4 v = ((const float4*)sdata)[k];
        float l = fmaf(v.x, w0, fmaf(v.y, w1, fmaf(v.z, w2, fmaf(v.w, w3, bb))));
        sout[k] = table_eval(l, stab);
    }
}

extern "C" void kernel_launch(void* const* d_in, const int* in_sizes, int n_in,
                              void* d_out, int out_size) {
    const float* data   = (const float*)d_in[0];   // [N, 2, 2]
    const float* conv_w = (const float*)d_in[1];   // [2, 2]
    const float* conv_b = (const float*)d_in[2];   // [1]
    const float* basis  = (const float*)d_in[3];   // [8, 4]
    const float* w1     = (const float*)d_in[4];   // [8, 16]
    const float* b1     = (const float*)d_in[5];   // [16]
    const float* w2     = (const float*)d_in[6];   // [16, 1]
    const float* b2     = (const float*)d_in[7];   // [1]

    const int n  = in_sizes[0] / 4;  // patches
    const int n4 = n / 4;

    // (NTAB+1)*16 = 32784 threads -> 129 blocks of 256
    int bblocks = ((NTAB + 1) * 16 + 255) / 256;
    build_table_kernel<<<bblocks, 256>>>(basis, w1, b1, w2, b2);

    // 1216 blocks = 8 CTAs/SM on 152 SMs
    hybridconv_main_kernel<<<1216, 256>>>(
        (const float4*)data, conv_w, conv_b, (float4*)d_out, n4, n);
}